// round 9
// baseline (speedup 1.0000x reference)
#include <cuda_runtime.h>
#include <cuda.h>
#include <cuda_bf16.h>
#include <cstdint>

// ============================================================================
// TT_Linear2: out[8192,4096] = X[8192,4096] @ W[4096,4096] + bias
// W materialized from TT cores:  W = (c0*c1) * (c2*c3)   (~0.54 GMACs)
// R8: GEMM reverted to R6 config (2048 CTAs, 128x128, 3-stage TMA ring,
//     2 CTAs/SM, boundary-after-MMAs, RR producer) -- best measured.
//     Prologue: build_wt fused with convert_x in one launch.
// ============================================================================

#define MDIM 8192
#define NDIM 4096
#define KDIM 4096

#define TM 128
#define TN 128
#define TK 64
#define STAGES 3
#define KITERS (KDIM / TK)          // 64
#define ABYTES (TM * TK * 2)        // 16384
#define BBYTES (TN * TK * 2)        // 16384
#define STAGE_BYTES (ABYTES + BBYTES)
#define SMEM_BYTES (1024 + STAGES * STAGE_BYTES)   // 99328

// ------------------------- device scratch (no cudaMalloc allowed) ----------
__device__ __align__(1024) float g_A01[131072];               // [i0,o0,i1,o1,r2]
__device__ __align__(1024) float g_A23[131072];               // [r2,i2,o2,i3,o3]
__device__ __align__(1024) __nv_bfloat16 g_Wt[(size_t)NDIM * KDIM];  // [n][k]
__device__ __align__(1024) __nv_bfloat16 g_xb[(size_t)MDIM * KDIM];  // [m][k]

// ------------------------- PTX helpers --------------------------------------
#define DEVI __device__ __forceinline__

DEVI uint32_t smem_u32(const void* p) {
    return (uint32_t)__cvta_generic_to_shared(p);
}

DEVI void mbar_init(uint32_t addr, uint32_t cnt) {
    asm volatile("mbarrier.init.shared.b64 [%0], %1;" :: "r"(addr), "r"(cnt) : "memory");
}

DEVI void mbar_arrive(uint32_t addr) {
    asm volatile("mbarrier.arrive.shared.b64 _, [%0];" :: "r"(addr) : "memory");
}

DEVI void mbar_expect_tx(uint32_t addr, uint32_t bytes) {
    asm volatile("mbarrier.arrive.expect_tx.shared.b64 _, [%0], %1;"
                 :: "r"(addr), "r"(bytes) : "memory");
}

DEVI void mbar_wait(uint32_t addr, uint32_t parity) {
    asm volatile(
        "{\n\t.reg .pred P1;\n\t"
        "LAB_WAIT_%=:\n\t"
        "mbarrier.try_wait.parity.acquire.cta.shared::cta.b64 P1, [%0], %1, 0x989680;\n\t"
        "@P1 bra.uni LAB_DONE_%=;\n\t"
        "bra.uni LAB_WAIT_%=;\n\t"
        "LAB_DONE_%=:\n\t}"
        :: "r"(addr), "r"(parity) : "memory");
}

DEVI void fence_proxy_async_cta() {
    asm volatile("fence.proxy.async.shared::cta;" ::: "memory");
}

DEVI void tma_load_2d(uint32_t dst, const CUtensorMap* map, int cx, int cy, uint32_t mbar) {
    asm volatile(
        "cp.async.bulk.tensor.2d.shared::cta.global.tile.mbarrier::complete_tx::bytes "
        "[%0], [%1, {%2, %3}], [%4];"
        :: "r"(dst), "l"(map), "r"(cx), "r"(cy), "r"(mbar) : "memory");
}

DEVI void ldsm_x4(uint32_t& r0, uint32_t& r1, uint32_t& r2, uint32_t& r3, uint32_t addr) {
    asm volatile("ldmatrix.sync.aligned.m8n8.x4.shared.b16 {%0,%1,%2,%3}, [%4];"
                 : "=r"(r0), "=r"(r1), "=r"(r2), "=r"(r3) : "r"(addr));
}

DEVI void mma_bf16(float* d, const uint32_t* a, uint32_t b0, uint32_t b1) {
    asm volatile(
        "mma.sync.aligned.m16n8k16.row.col.f32.bf16.bf16.f32 "
        "{%0,%1,%2,%3}, {%4,%5,%6,%7}, {%8,%9}, {%0,%1,%2,%3};"
        : "+f"(d[0]), "+f"(d[1]), "+f"(d[2]), "+f"(d[3])
        : "r"(a[0]), "r"(a[1]), "r"(a[2]), "r"(a[3]), "r"(b0), "r"(b1));
}

// ============================================================================
// Kernel 1: pairwise core contractions (one pass, 128 blocks x 256 thr)
// ============================================================================
__global__ void build_a_kernel(const float* __restrict__ c0, const float* __restrict__ c1,
                               const float* __restrict__ c2, const float* __restrict__ c3) {
    int idx = blockIdx.x * 256 + threadIdx.x;
    {
        // A01 element  (idx in [0,131072) covered by blocks 0..511 of 2048-range)
        int half = idx >> 17;        // 0: A01, 1: A23
        int j = idx & 131071;
        if (half == 0) {
            int r2 = j & 31;
            int t4 = j >> 5;  // ((i0*8+o0)*8+i1)*8+o1
            int o1 = t4 & 7, i1 = (t4 >> 3) & 7, o0 = (t4 >> 6) & 7, i0 = (t4 >> 9) & 7;
            float acc = 0.f;
            #pragma unroll
            for (int r1 = 0; r1 < 32; ++r1)
                acc += c0[(i0 * 8 + o0) * 32 + r1] * c1[((r1 * 8 + i1) * 8 + o1) * 32 + r2];
            g_A01[j] = acc;
        } else {
            int o3 = j & 7, i3 = (j >> 3) & 7, o2 = (j >> 6) & 7, i2 = (j >> 9) & 7, r2 = j >> 12;
            float acc = 0.f;
            #pragma unroll
            for (int r3 = 0; r3 < 32; ++r3)
                acc += c2[((r2 * 8 + i2) * 8 + o2) * 32 + r3] * c3[(r3 * 8 + i3) * 8 + o3];
            g_A23[j] = acc;
        }
    }
}

// ============================================================================
// Kernel 2 (fused): blocks [0,1024)   -> Wt build (reads g_A01/g_A23)
//                   blocks [1024,5120) -> X fp32 -> bf16 convert
// ============================================================================
__global__ void wt_and_convert_kernel(const float4* __restrict__ x4) {
    __shared__ float vsh[2048];
    int t = threadIdx.x;

    if (blockIdx.x < 1024) {
        int g  = blockIdx.x & 63;   // tile group 0..63
        int eb = blockIdx.x >> 6;   // element block 0..15
        int e = eb * 256 + t;
        int a = e >> 6, b = e & 63;                 // a=(o2,o3), b=(i2,i3)
        int i2 = b >> 3, i3 = b & 7, o2 = a >> 3, o3 = a & 7;

        float m[32];
        #pragma unroll
        for (int r2 = 0; r2 < 32; ++r2)
            m[r2] = g_A23[r2 * 4096 + (i2 * 8 + o2) * 64 + i3 * 8 + o3];

        for (int idx = t; idx < 2048; idx += 256)
            vsh[idx] = g_A01[g * 2048 + idx];
        __syncthreads();

        for (int tt = 0; tt < 64; ++tt) {
            int t4 = g * 64 + tt;
            int o1 = t4 & 7, i1 = (t4 >> 3) & 7, o0 = (t4 >> 6) & 7, i0 = (t4 >> 9) & 7;
            float acc = 0.f;
            #pragma unroll
            for (int r2 = 0; r2 < 32; ++r2)
                acc += vsh[tt * 32 + r2] * m[r2];
            int n = o0 * 512 + o1 * 64 + a;
            int k = i0 * 512 + i1 * 64 + b;
            g_Wt[(size_t)n * KDIM + k] = __float2bfloat16(acc);
        }
    } else {
        int bid = blockIdx.x - 1024;   // 0..4095
        const int total = (MDIM * KDIM) / 4;   // 8388608
        uint2* dst = reinterpret_cast<uint2*>(g_xb);
        for (int i = bid * 256 + t; i < total; i += 4096 * 256) {
            float4 v = x4[i];
            __nv_bfloat162 p0 = __floats2bfloat162_rn(v.x, v.y);
            __nv_bfloat162 p1 = __floats2bfloat162_rn(v.z, v.w);
            uint2 u;
            u.x = *reinterpret_cast<unsigned*>(&p0);
            u.y = *reinterpret_cast<unsigned*>(&p1);
            dst[i] = u;
        }
    }
}

// ============================================================================
// Kernel 3: GEMM  out = Xb @ Wt^T + bias   (R6 config -- best measured)
//   CTA tile 128x128, TK=64, 3-stage TMA pipeline, 4 warps (2x2), 2 CTAs/SM.
//   Stage-boundary waits AFTER all ready MMAs; round-robin producer warp.
// ============================================================================
__global__ void __launch_bounds__(128, 2)
gemm_kernel(const __grid_constant__ CUtensorMap tmA,
            const __grid_constant__ CUtensorMap tmB,
            const float* __restrict__ bias,
            float* __restrict__ out) {
    extern __shared__ char smem[];
    uint32_t smem_base = smem_u32(smem);
    uint32_t mb_full  = smem_base;                  // 3 x 8B
    uint32_t mb_empty = smem_base + 32;             // 3 x 8B
    uint32_t sb = (smem_base + 1024) & ~1023u;      // 1024-aligned tile area
    uint32_t uA = sb;                               // 3 x 16KB
    uint32_t uB = sb + STAGES * ABYTES;             // 3 x 16KB

    int tid = threadIdx.x;
    int wid = tid >> 5;
    int lid = tid & 31;
    int n0 = blockIdx.x * TN;
    int m0 = blockIdx.y * TM;

    int warpM = (wid >> 1) * 64;    // 0 or 64
    int warpN = (wid & 1) * 64;     // 0 or 64

    if (tid == 0) {
        #pragma unroll
        for (int s = 0; s < STAGES; ++s) {
            mbar_init(mb_full + 8 * s, 1);
            mbar_init(mb_empty + 8 * s, 4);   // one arrive per warp
        }
        fence_proxy_async_cta();
    }
    __syncthreads();

    // ---- prologue: fill STAGES-1 stages ----
    if (tid == 0) {
        #pragma unroll
        for (int s = 0; s < STAGES - 1; ++s) {
            mbar_expect_tx(mb_full + 8 * s, STAGE_BYTES);
            tma_load_2d(uA + s * ABYTES, &tmA, s * TK, m0, mb_full + 8 * s);
            tma_load_2d(uB + s * BBYTES, &tmB, s * TK, n0, mb_full + 8 * s);
        }
    }

    // per-lane ldmatrix addressing pieces (SW128 swizzle: chunk ^= row&7)
    int lrow = lid & 15;           // row within 16-row ldmatrix group
    int lhi  = lid >> 4;           // 16B chunk selector

    float acc[4][8][4];
    #pragma unroll
    for (int mi = 0; mi < 4; ++mi)
        #pragma unroll
        for (int ni = 0; ni < 8; ++ni)
            #pragma unroll
            for (int j = 0; j < 4; ++j) acc[mi][ni][j] = 0.f;

    uint32_t aRowOff[4], aRow7[4];
    #pragma unroll
    for (int mi = 0; mi < 4; ++mi) {
        int r = warpM + mi * 16 + lrow;
        aRowOff[mi] = (uint32_t)r * 128;
        aRow7[mi] = (uint32_t)(r & 7);
    }
    uint32_t bRowOff[4], bRow7[4];
    #pragma unroll
    for (int nt = 0; nt < 4; ++nt) {
        int r = warpN + nt * 16 + lrow;
        bRowOff[nt] = (uint32_t)r * 128;
        bRow7[nt] = (uint32_t)(r & 7);
    }

    // double-buffered fragments
    uint32_t afrag[2][4][4], bfrag[2][4][4];

    auto load_chunk = [&](int buf, uint32_t aBase, uint32_t bBase, int kc) {
        uint32_t chunk = (uint32_t)(kc * 2 + lhi);
        #pragma unroll
        for (int mi = 0; mi < 4; ++mi) {
            uint32_t addr = aBase + aRowOff[mi] + ((chunk ^ aRow7[mi]) << 4);
            ldsm_x4(afrag[buf][mi][0], afrag[buf][mi][1],
                    afrag[buf][mi][2], afrag[buf][mi][3], addr);
        }
        #pragma unroll
        for (int nt = 0; nt < 4; ++nt) {
            uint32_t addr = bBase + bRowOff[nt] + ((chunk ^ bRow7[nt]) << 4);
            ldsm_x4(bfrag[buf][nt][0], bfrag[buf][nt][1],
                    bfrag[buf][nt][2], bfrag[buf][nt][3], addr);
        }
    };

    auto mma_block = [&](int cur) {
        #pragma unroll
        for (int mi = 0; mi < 4; ++mi) {
            #pragma unroll
            for (int nt = 0; nt < 4; ++nt) {
                mma_bf16(acc[mi][nt * 2 + 0], afrag[cur][mi],
                         bfrag[cur][nt][0], bfrag[cur][nt][2]);
                mma_bf16(acc[mi][nt * 2 + 1], afrag[cur][mi],
                         bfrag[cur][nt][1], bfrag[cur][nt][3]);
            }
        }
    };

    // pipeline cursors (STAGES=3 -> explicit wrap)
    int cs = 0, cph = 0;            // consumer: stage, full-parity
    int ps = STAGES - 1, pph = 1;   // producer: refill stage (it+2), empty-parity

    // wait stage 0 and preload its chunk 0
    mbar_wait(mb_full, 0);
    load_chunk(0, uA, uB, 0);

    for (int it = 0; it < KITERS; ++it) {
        uint32_t aBase = uA + cs * ABYTES;
        uint32_t bBase = uB + cs * BBYTES;

        // chunks 0..3: prefetch next chunk, then MMA current (all ready work)
        #pragma unroll
        for (int j = 0; j < 4; ++j) {
            int cur = j & 1;
            if (j < 3) load_chunk(cur ^ 1, aBase, bBase, j + 1);
            mma_block(cur);
        }

        // ---- stage boundary (only blocking waits live here) ----
        if (lid == 0) mbar_arrive(mb_empty + 8 * cs);

        // round-robin producer warp: refill stage it+2
        if (wid == (it & 3) && lid == 0) {
            int n = it + STAGES - 1;
            if (n < KITERS) {
                mbar_wait(mb_empty + 8 * ps, pph);
                mbar_expect_tx(mb_full + 8 * ps, STAGE_BYTES);
                tma_load_2d(uA + ps * ABYTES, &tmA, n * TK, m0, mb_full + 8 * ps);
                tma_load_2d(uB + ps * BBYTES, &tmB, n * TK, n0, mb_full + 8 * ps);
            }
        }
        if (++ps == STAGES) { ps = 0; pph ^= 1; }

        int ns = cs + 1, nph = cph;
        if (ns == STAGES) { ns = 0; nph ^= 1; }
        if (it + 1 < KITERS) {
            mbar_wait(mb_full + 8 * ns, nph);
            load_chunk(0, uA + ns * ABYTES, uB + ns * BBYTES, 0);
        }
        cs = ns; cph = nph;
    }

    // ---- epilogue: fp32 + bias, float2 stores ----
    int rbase = m0 + warpM + (lid >> 2);
    int cbase = n0 + warpN + (lid & 3) * 2;
    #pragma unroll
    for (int mi = 0; mi < 4; ++mi) {
        #pragma unroll
        for (int ni = 0; ni < 8; ++ni) {
            int col = cbase + ni * 8;
            float2 bv = *reinterpret_cast<const float2*>(bias + col);
            int r0 = rbase + mi * 16;
            float2 v0, v1;
            v0.x = acc[mi][ni][0] + bv.x;
            v0.y = acc[mi][ni][1] + bv.y;
            v1.x = acc[mi][ni][2] + bv.x;
            v1.y = acc[mi][ni][3] + bv.y;
            *reinterpret_cast<float2*>(out + (size_t)r0 * NDIM + col) = v0;
            *reinterpret_cast<float2*>(out + (size_t)(r0 + 8) * NDIM + col) = v1;
        }
    }
}

// ============================================================================
// Host side
// ============================================================================
typedef CUresult (*EncodeTiledFn)(
    CUtensorMap*, CUtensorMapDataType, cuuint32_t, void*,
    const cuuint64_t*, const cuuint64_t*, const cuuint32_t*, const cuuint32_t*,
    CUtensorMapInterleave, CUtensorMapSwizzle, CUtensorMapL2promotion,
    CUtensorMapFloatOOBfill);

extern "C" void kernel_launch(void* const* d_in, const int* in_sizes, int n_in,
                              void* d_out, int out_size) {
    const float* x    = (const float*)d_in[0];
    const float* c0   = (const float*)d_in[1];
    const float* c1   = (const float*)d_in[2];
    const float* c2   = (const float*)d_in[3];
    const float* c3   = (const float*)d_in[4];
    const float* bias = (const float*)d_in[5];
    float* out = (float*)d_out;

    void* wt_ptr = nullptr;
    void* xb_ptr = nullptr;
    cudaGetSymbolAddress(&wt_ptr, g_Wt);
    cudaGetSymbolAddress(&xb_ptr, g_xb);

    EncodeTiledFn encode = nullptr;
    cudaDriverEntryPointQueryResult qr;
    cudaGetDriverEntryPointByVersion("cuTensorMapEncodeTiled", (void**)&encode,
                                     12000, cudaEnableDefault, &qr);

    CUtensorMap tmA, tmB;
    {
        cuuint64_t dims[2]    = {KDIM, MDIM};
        cuuint64_t strides[1] = {KDIM * 2};
        cuuint32_t box[2]     = {TK, TM};
        cuuint32_t es[2]      = {1, 1};
        encode(&tmA, CU_TENSOR_MAP_DATA_TYPE_BFLOAT16, 2, xb_ptr, dims, strides,
               box, es, CU_TENSOR_MAP_INTERLEAVE_NONE, CU_TENSOR_MAP_SWIZZLE_128B,
               CU_TENSOR_MAP_L2_PROMOTION_L2_128B, CU_TENSOR_MAP_FLOAT_OOB_FILL_NONE);
    }
    {
        cuuint64_t dims[2]    = {KDIM, NDIM};
        cuuint64_t strides[1] = {KDIM * 2};
        cuuint32_t box[2]     = {TK, TN};
        cuuint32_t es[2]      = {1, 1};
        encode(&tmB, CU_TENSOR_MAP_DATA_TYPE_BFLOAT16, 2, wt_ptr, dims, strides,
               box, es, CU_TENSOR_MAP_INTERLEAVE_NONE, CU_TENSOR_MAP_SWIZZLE_128B,
               CU_TENSOR_MAP_L2_PROMOTION_L2_128B, CU_TENSOR_MAP_FLOAT_OOB_FILL_NONE);
    }

    cudaFuncSetAttribute(gemm_kernel, cudaFuncAttributeMaxDynamicSharedMemorySize,
                         SMEM_BYTES);

    build_a_kernel<<<1024, 256>>>(c0, c1, c2, c3);
    wt_and_convert_kernel<<<5120, 256>>>((const float4*)x);
    gemm_kernel<<<dim3(NDIM / TN, MDIM / TM), 128, SMEM_BYTES>>>(tmA, tmB, bias, out);
}

// round 10
// speedup vs baseline: 1.0014x; 1.0014x over previous
#include <cuda_runtime.h>
#include <cuda.h>
#include <cuda_bf16.h>
#include <cstdint>

// ============================================================================
// TT_Linear2: out[8192,4096] = X[8192,4096] @ W[4096,4096] + bias
// W materialized from TT cores:  W = (c0*c1) * (c2*c3)   (~0.54 GMACs)
// R8: GEMM reverted to R6 config (2048 CTAs, 128x128, 3-stage TMA ring,
//     2 CTAs/SM, boundary-after-MMAs, RR producer) -- best measured.
//     Prologue: build_wt fused with convert_x in one launch.
// ============================================================================

#define MDIM 8192
#define NDIM 4096
#define KDIM 4096

#define TM 128
#define TN 128
#define TK 64
#define STAGES 3
#define KITERS (KDIM / TK)          // 64
#define ABYTES (TM * TK * 2)        // 16384
#define BBYTES (TN * TK * 2)        // 16384
#define STAGE_BYTES (ABYTES + BBYTES)
#define SMEM_BYTES (1024 + STAGES * STAGE_BYTES)   // 99328

// ------------------------- device scratch (no cudaMalloc allowed) ----------
__device__ __align__(1024) float g_A01[131072];               // [i0,o0,i1,o1,r2]
__device__ __align__(1024) float g_A23[131072];               // [r2,i2,o2,i3,o3]
__device__ __align__(1024) __nv_bfloat16 g_Wt[(size_t)NDIM * KDIM];  // [n][k]
__device__ __align__(1024) __nv_bfloat16 g_xb[(size_t)MDIM * KDIM];  // [m][k]

// ------------------------- PTX helpers --------------------------------------
#define DEVI __device__ __forceinline__

DEVI uint32_t smem_u32(const void* p) {
    return (uint32_t)__cvta_generic_to_shared(p);
}

DEVI void mbar_init(uint32_t addr, uint32_t cnt) {
    asm volatile("mbarrier.init.shared.b64 [%0], %1;" :: "r"(addr), "r"(cnt) : "memory");
}

DEVI void mbar_arrive(uint32_t addr) {
    asm volatile("mbarrier.arrive.shared.b64 _, [%0];" :: "r"(addr) : "memory");
}

DEVI void mbar_expect_tx(uint32_t addr, uint32_t bytes) {
    asm volatile("mbarrier.arrive.expect_tx.shared.b64 _, [%0], %1;"
                 :: "r"(addr), "r"(bytes) : "memory");
}

DEVI void mbar_wait(uint32_t addr, uint32_t parity) {
    asm volatile(
        "{\n\t.reg .pred P1;\n\t"
        "LAB_WAIT_%=:\n\t"
        "mbarrier.try_wait.parity.acquire.cta.shared::cta.b64 P1, [%0], %1, 0x989680;\n\t"
        "@P1 bra.uni LAB_DONE_%=;\n\t"
        "bra.uni LAB_WAIT_%=;\n\t"
        "LAB_DONE_%=:\n\t}"
        :: "r"(addr), "r"(parity) : "memory");
}

DEVI void fence_proxy_async_cta() {
    asm volatile("fence.proxy.async.shared::cta;" ::: "memory");
}

DEVI void tma_load_2d(uint32_t dst, const CUtensorMap* map, int cx, int cy, uint32_t mbar) {
    asm volatile(
        "cp.async.bulk.tensor.2d.shared::cta.global.tile.mbarrier::complete_tx::bytes "
        "[%0], [%1, {%2, %3}], [%4];"
        :: "r"(dst), "l"(map), "r"(cx), "r"(cy), "r"(mbar) : "memory");
}

DEVI void ldsm_x4(uint32_t& r0, uint32_t& r1, uint32_t& r2, uint32_t& r3, uint32_t addr) {
    asm volatile("ldmatrix.sync.aligned.m8n8.x4.shared.b16 {%0,%1,%2,%3}, [%4];"
                 : "=r"(r0), "=r"(r1), "=r"(r2), "=r"(r3) : "r"(addr));
}

DEVI void mma_bf16(float* d, const uint32_t* a, uint32_t b0, uint32_t b1) {
    asm volatile(
        "mma.sync.aligned.m16n8k16.row.col.f32.bf16.bf16.f32 "
        "{%0,%1,%2,%3}, {%4,%5,%6,%7}, {%8,%9}, {%0,%1,%2,%3};"
        : "+f"(d[0]), "+f"(d[1]), "+f"(d[2]), "+f"(d[3])
        : "r"(a[0]), "r"(a[1]), "r"(a[2]), "r"(a[3]), "r"(b0), "r"(b1));
}

// ============================================================================
// Kernel 1: pairwise core contractions (one pass, 128 blocks x 256 thr)
// ============================================================================
__global__ void build_a_kernel(const float* __restrict__ c0, const float* __restrict__ c1,
                               const float* __restrict__ c2, const float* __restrict__ c3) {
    int idx = blockIdx.x * 256 + threadIdx.x;
    {
        // A01 element  (idx in [0,131072) covered by blocks 0..511 of 2048-range)
        int half = idx >> 17;        // 0: A01, 1: A23
        int j = idx & 131071;
        if (half == 0) {
            int r2 = j & 31;
            int t4 = j >> 5;  // ((i0*8+o0)*8+i1)*8+o1
            int o1 = t4 & 7, i1 = (t4 >> 3) & 7, o0 = (t4 >> 6) & 7, i0 = (t4 >> 9) & 7;
            float acc = 0.f;
            #pragma unroll
            for (int r1 = 0; r1 < 32; ++r1)
                acc += c0[(i0 * 8 + o0) * 32 + r1] * c1[((r1 * 8 + i1) * 8 + o1) * 32 + r2];
            g_A01[j] = acc;
        } else {
            int o3 = j & 7, i3 = (j >> 3) & 7, o2 = (j >> 6) & 7, i2 = (j >> 9) & 7, r2 = j >> 12;
            float acc = 0.f;
            #pragma unroll
            for (int r3 = 0; r3 < 32; ++r3)
                acc += c2[((r2 * 8 + i2) * 8 + o2) * 32 + r3] * c3[(r3 * 8 + i3) * 8 + o3];
            g_A23[j] = acc;
        }
    }
}

// ============================================================================
// Kernel 2 (fused): blocks [0,1024)   -> Wt build (reads g_A01/g_A23)
//                   blocks [1024,5120) -> X fp32 -> bf16 convert
// ============================================================================
__global__ void wt_and_convert_kernel(const float4* __restrict__ x4) {
    __shared__ float vsh[2048];
    int t = threadIdx.x;

    if (blockIdx.x < 1024) {
        int g  = blockIdx.x & 63;   // tile group 0..63
        int eb = blockIdx.x >> 6;   // element block 0..15
        int e = eb * 256 + t;
        int a = e >> 6, b = e & 63;                 // a=(o2,o3), b=(i2,i3)
        int i2 = b >> 3, i3 = b & 7, o2 = a >> 3, o3 = a & 7;

        float m[32];
        #pragma unroll
        for (int r2 = 0; r2 < 32; ++r2)
            m[r2] = g_A23[r2 * 4096 + (i2 * 8 + o2) * 64 + i3 * 8 + o3];

        for (int idx = t; idx < 2048; idx += 256)
            vsh[idx] = g_A01[g * 2048 + idx];
        __syncthreads();

        for (int tt = 0; tt < 64; ++tt) {
            int t4 = g * 64 + tt;
            int o1 = t4 & 7, i1 = (t4 >> 3) & 7, o0 = (t4 >> 6) & 7, i0 = (t4 >> 9) & 7;
            float acc = 0.f;
            #pragma unroll
            for (int r2 = 0; r2 < 32; ++r2)
                acc += vsh[tt * 32 + r2] * m[r2];
            int n = o0 * 512 + o1 * 64 + a;
            int k = i0 * 512 + i1 * 64 + b;
            g_Wt[(size_t)n * KDIM + k] = __float2bfloat16(acc);
        }
    } else {
        int bid = blockIdx.x - 1024;   // 0..4095
        const int total = (MDIM * KDIM) / 4;   // 8388608
        uint2* dst = reinterpret_cast<uint2*>(g_xb);
        for (int i = bid * 256 + t; i < total; i += 4096 * 256) {
            float4 v = x4[i];
            __nv_bfloat162 p0 = __floats2bfloat162_rn(v.x, v.y);
            __nv_bfloat162 p1 = __floats2bfloat162_rn(v.z, v.w);
            uint2 u;
            u.x = *reinterpret_cast<unsigned*>(&p0);
            u.y = *reinterpret_cast<unsigned*>(&p1);
            dst[i] = u;
        }
    }
}

// ============================================================================
// Kernel 3: GEMM  out = Xb @ Wt^T + bias   (R6 config -- best measured)
//   CTA tile 128x128, TK=64, 3-stage TMA pipeline, 4 warps (2x2), 2 CTAs/SM.
//   Stage-boundary waits AFTER all ready MMAs; round-robin producer warp.
// ============================================================================
__global__ void __launch_bounds__(128, 2)
gemm_kernel(const __grid_constant__ CUtensorMap tmA,
            const __grid_constant__ CUtensorMap tmB,
            const float* __restrict__ bias,
            float* __restrict__ out) {
    extern __shared__ char smem[];
    uint32_t smem_base = smem_u32(smem);
    uint32_t mb_full  = smem_base;                  // 3 x 8B
    uint32_t mb_empty = smem_base + 32;             // 3 x 8B
    uint32_t sb = (smem_base + 1024) & ~1023u;      // 1024-aligned tile area
    uint32_t uA = sb;                               // 3 x 16KB
    uint32_t uB = sb + STAGES * ABYTES;             // 3 x 16KB

    int tid = threadIdx.x;
    int wid = tid >> 5;
    int lid = tid & 31;
    int n0 = blockIdx.x * TN;
    int m0 = blockIdx.y * TM;

    int warpM = (wid >> 1) * 64;    // 0 or 64
    int warpN = (wid & 1) * 64;     // 0 or 64

    if (tid == 0) {
        #pragma unroll
        for (int s = 0; s < STAGES; ++s) {
            mbar_init(mb_full + 8 * s, 1);
            mbar_init(mb_empty + 8 * s, 4);   // one arrive per warp
        }
        fence_proxy_async_cta();
    }
    __syncthreads();

    // ---- prologue: fill STAGES-1 stages ----
    if (tid == 0) {
        #pragma unroll
        for (int s = 0; s < STAGES - 1; ++s) {
            mbar_expect_tx(mb_full + 8 * s, STAGE_BYTES);
            tma_load_2d(uA + s * ABYTES, &tmA, s * TK, m0, mb_full + 8 * s);
            tma_load_2d(uB + s * BBYTES, &tmB, s * TK, n0, mb_full + 8 * s);
        }
    }

    // per-lane ldmatrix addressing pieces (SW128 swizzle: chunk ^= row&7)
    int lrow = lid & 15;           // row within 16-row ldmatrix group
    int lhi  = lid >> 4;           // 16B chunk selector

    float acc[4][8][4];
    #pragma unroll
    for (int mi = 0; mi < 4; ++mi)
        #pragma unroll
        for (int ni = 0; ni < 8; ++ni)
            #pragma unroll
            for (int j = 0; j < 4; ++j) acc[mi][ni][j] = 0.f;

    uint32_t aRowOff[4], aRow7[4];
    #pragma unroll
    for (int mi = 0; mi < 4; ++mi) {
        int r = warpM + mi * 16 + lrow;
        aRowOff[mi] = (uint32_t)r * 128;
        aRow7[mi] = (uint32_t)(r & 7);
    }
    uint32_t bRowOff[4], bRow7[4];
    #pragma unroll
    for (int nt = 0; nt < 4; ++nt) {
        int r = warpN + nt * 16 + lrow;
        bRowOff[nt] = (uint32_t)r * 128;
        bRow7[nt] = (uint32_t)(r & 7);
    }

    // double-buffered fragments
    uint32_t afrag[2][4][4], bfrag[2][4][4];

    auto load_chunk = [&](int buf, uint32_t aBase, uint32_t bBase, int kc) {
        uint32_t chunk = (uint32_t)(kc * 2 + lhi);
        #pragma unroll
        for (int mi = 0; mi < 4; ++mi) {
            uint32_t addr = aBase + aRowOff[mi] + ((chunk ^ aRow7[mi]) << 4);
            ldsm_x4(afrag[buf][mi][0], afrag[buf][mi][1],
                    afrag[buf][mi][2], afrag[buf][mi][3], addr);
        }
        #pragma unroll
        for (int nt = 0; nt < 4; ++nt) {
            uint32_t addr = bBase + bRowOff[nt] + ((chunk ^ bRow7[nt]) << 4);
            ldsm_x4(bfrag[buf][nt][0], bfrag[buf][nt][1],
                    bfrag[buf][nt][2], bfrag[buf][nt][3], addr);
        }
    };

    auto mma_block = [&](int cur) {
        #pragma unroll
        for (int mi = 0; mi < 4; ++mi) {
            #pragma unroll
            for (int nt = 0; nt < 4; ++nt) {
                mma_bf16(acc[mi][nt * 2 + 0], afrag[cur][mi],
                         bfrag[cur][nt][0], bfrag[cur][nt][2]);
                mma_bf16(acc[mi][nt * 2 + 1], afrag[cur][mi],
                         bfrag[cur][nt][1], bfrag[cur][nt][3]);
            }
        }
    };

    // pipeline cursors (STAGES=3 -> explicit wrap)
    int cs = 0, cph = 0;            // consumer: stage, full-parity
    int ps = STAGES - 1, pph = 1;   // producer: refill stage (it+2), empty-parity

    // wait stage 0 and preload its chunk 0
    mbar_wait(mb_full, 0);
    load_chunk(0, uA, uB, 0);

    for (int it = 0; it < KITERS; ++it) {
        uint32_t aBase = uA + cs * ABYTES;
        uint32_t bBase = uB + cs * BBYTES;

        // chunks 0..3: prefetch next chunk, then MMA current (all ready work)
        #pragma unroll
        for (int j = 0; j < 4; ++j) {
            int cur = j & 1;
            if (j < 3) load_chunk(cur ^ 1, aBase, bBase, j + 1);
            mma_block(cur);
        }

        // ---- stage boundary (only blocking waits live here) ----
        if (lid == 0) mbar_arrive(mb_empty + 8 * cs);

        // round-robin producer warp: refill stage it+2
        if (wid == (it & 3) && lid == 0) {
            int n = it + STAGES - 1;
            if (n < KITERS) {
                mbar_wait(mb_empty + 8 * ps, pph);
                mbar_expect_tx(mb_full + 8 * ps, STAGE_BYTES);
                tma_load_2d(uA + ps * ABYTES, &tmA, n * TK, m0, mb_full + 8 * ps);
                tma_load_2d(uB + ps * BBYTES, &tmB, n * TK, n0, mb_full + 8 * ps);
            }
        }
        if (++ps == STAGES) { ps = 0; pph ^= 1; }

        int ns = cs + 1, nph = cph;
        if (ns == STAGES) { ns = 0; nph ^= 1; }
        if (it + 1 < KITERS) {
            mbar_wait(mb_full + 8 * ns, nph);
            load_chunk(0, uA + ns * ABYTES, uB + ns * BBYTES, 0);
        }
        cs = ns; cph = nph;
    }

    // ---- epilogue: fp32 + bias, float2 stores ----
    int rbase = m0 + warpM + (lid >> 2);
    int cbase = n0 + warpN + (lid & 3) * 2;
    #pragma unroll
    for (int mi = 0; mi < 4; ++mi) {
        #pragma unroll
        for (int ni = 0; ni < 8; ++ni) {
            int col = cbase + ni * 8;
            float2 bv = *reinterpret_cast<const float2*>(bias + col);
            int r0 = rbase + mi * 16;
            float2 v0, v1;
            v0.x = acc[mi][ni][0] + bv.x;
            v0.y = acc[mi][ni][1] + bv.y;
            v1.x = acc[mi][ni][2] + bv.x;
            v1.y = acc[mi][ni][3] + bv.y;
            *reinterpret_cast<float2*>(out + (size_t)r0 * NDIM + col) = v0;
            *reinterpret_cast<float2*>(out + (size_t)(r0 + 8) * NDIM + col) = v1;
        }
    }
}

// ============================================================================
// Host side
// ============================================================================
typedef CUresult (*EncodeTiledFn)(
    CUtensorMap*, CUtensorMapDataType, cuuint32_t, void*,
    const cuuint64_t*, const cuuint64_t*, const cuuint32_t*, const cuuint32_t*,
    CUtensorMapInterleave, CUtensorMapSwizzle, CUtensorMapL2promotion,
    CUtensorMapFloatOOBfill);

extern "C" void kernel_launch(void* const* d_in, const int* in_sizes, int n_in,
                              void* d_out, int out_size) {
    const float* x    = (const float*)d_in[0];
    const float* c0   = (const float*)d_in[1];
    const float* c1   = (const float*)d_in[2];
    const float* c2   = (const float*)d_in[3];
    const float* c3   = (const float*)d_in[4];
    const float* bias = (const float*)d_in[5];
    float* out = (float*)d_out;

    void* wt_ptr = nullptr;
    void* xb_ptr = nullptr;
    cudaGetSymbolAddress(&wt_ptr, g_Wt);
    cudaGetSymbolAddress(&xb_ptr, g_xb);

    EncodeTiledFn encode = nullptr;
    cudaDriverEntryPointQueryResult qr;
    cudaGetDriverEntryPointByVersion("cuTensorMapEncodeTiled", (void**)&encode,
                                     12000, cudaEnableDefault, &qr);

    CUtensorMap tmA, tmB;
    {
        cuuint64_t dims[2]    = {KDIM, MDIM};
        cuuint64_t strides[1] = {KDIM * 2};
        cuuint32_t box[2]     = {TK, TM};
        cuuint32_t es[2]      = {1, 1};
        encode(&tmA, CU_TENSOR_MAP_DATA_TYPE_BFLOAT16, 2, xb_ptr, dims, strides,
               box, es, CU_TENSOR_MAP_INTERLEAVE_NONE, CU_TENSOR_MAP_SWIZZLE_128B,
               CU_TENSOR_MAP_L2_PROMOTION_L2_128B, CU_TENSOR_MAP_FLOAT_OOB_FILL_NONE);
    }
    {
        cuuint64_t dims[2]    = {KDIM, NDIM};
        cuuint64_t strides[1] = {KDIM * 2};
        cuuint32_t box[2]     = {TK, TN};
        cuuint32_t es[2]      = {1, 1};
        encode(&tmB, CU_TENSOR_MAP_DATA_TYPE_BFLOAT16, 2, wt_ptr, dims, strides,
               box, es, CU_TENSOR_MAP_INTERLEAVE_NONE, CU_TENSOR_MAP_SWIZZLE_128B,
               CU_TENSOR_MAP_L2_PROMOTION_L2_128B, CU_TENSOR_MAP_FLOAT_OOB_FILL_NONE);
    }

    cudaFuncSetAttribute(gemm_kernel, cudaFuncAttributeMaxDynamicSharedMemorySize,
                         SMEM_BYTES);

    build_a_kernel<<<1024, 256>>>(c0, c1, c2, c3);
    wt_and_convert_kernel<<<5120, 256>>>((const float4*)x);
    gemm_kernel<<<dim3(NDIM / TN, MDIM / TM), 128, SMEM_BYTES>>>(tmA, tmB, bias, out);
}